// round 1
// baseline (speedup 1.0000x reference)
#include <cuda_runtime.h>

#define NB 2
#define N1 4096
#define N2 16384
#define CF 64
#define KNN 8

// Scratch (static __device__ arrays per allocation rules)
__device__ float4 g_pts[NB * N1];            // x, y, z, |p|^2           (128 KB)
__device__ float  g_gtab[NB * N1 * CF];      // W1_feat@feat + W1_xyz@xyz1 + b1  (2 MB)
__device__ int    g_idx[NB * N2 * KNN];      // knn indices              (1 MB)

// ---------------------------------------------------------------------------
// Kernel 1: pack xyz1 into float4 (x,y,z,t2) for the KNN scan
// ---------------------------------------------------------------------------
__global__ void pack_kernel(const float* __restrict__ xyz1) {
    int i = blockIdx.x * blockDim.x + threadIdx.x;
    if (i >= NB * N1) return;
    int b = i / N1, j = i - b * N1;
    const float* p = xyz1 + (size_t)b * 3 * N1;
    float x = p[j], y = p[N1 + j], z = p[2 * N1 + j];
    g_pts[i] = make_float4(x, y, z, x * x + y * y + z * z);
}

// ---------------------------------------------------------------------------
// Kernel 2: per-target transform  g[b][j][o] = sum_c W1[o][c]*in[c] + b1[o]
//           in = [feat1[:,j] (64) ; xyz1[:,j] (3)]
// One block = 64 targets, 256 threads: thread (o = t%64, jg = t/64) does 16 j.
// ---------------------------------------------------------------------------
__global__ void __launch_bounds__(256) gmat_kernel(const float* __restrict__ feat1,
                                                   const float* __restrict__ xyz1,
                                                   const float* __restrict__ W1,
                                                   const float* __restrict__ b1) {
    __shared__ __align__(16) float sIn[67 * 64];
    __shared__ float sW[64 * 67];
    __shared__ float sB[64];

    int b  = blockIdx.x >> 6;
    int j0 = (blockIdx.x & 63) * 64;
    int t  = threadIdx.x;

    for (int i = t; i < 64 * 67; i += 256) sW[i] = W1[i];
    if (t < 64) sB[t] = b1[t];

    const float* fb = feat1 + (size_t)b * CF * N1;
    for (int i = t; i < 64 * 64; i += 256) {
        int c = i >> 6, j = i & 63;
        sIn[c * 64 + j] = fb[c * N1 + j0 + j];
    }
    const float* xb = xyz1 + (size_t)b * 3 * N1;
    if (t < 3 * 64) {
        int c = t >> 6, j = t & 63;
        sIn[(64 + c) * 64 + j] = xb[c * N1 + j0 + j];
    }
    __syncthreads();

    int o = t & 63, jg = t >> 6;   // jg in 0..3, each covers 16 consecutive j
    float acc[16];
    float bb = sB[o];
#pragma unroll
    for (int ii = 0; ii < 16; ii++) acc[ii] = bb;

    for (int c = 0; c < 67; c++) {
        float w = sW[o * 67 + c];
        const float4* in4 = (const float4*)(sIn + c * 64 + jg * 16);
#pragma unroll
        for (int q4 = 0; q4 < 4; q4++) {
            float4 v = in4[q4];
            acc[q4 * 4 + 0] = fmaf(w, v.x, acc[q4 * 4 + 0]);
            acc[q4 * 4 + 1] = fmaf(w, v.y, acc[q4 * 4 + 1]);
            acc[q4 * 4 + 2] = fmaf(w, v.z, acc[q4 * 4 + 2]);
            acc[q4 * 4 + 3] = fmaf(w, v.w, acc[q4 * 4 + 3]);
        }
    }

    float* gp = g_gtab + ((size_t)b * N1 + j0 + jg * 16) * CF + o;
#pragma unroll
    for (int ii = 0; ii < 16; ii++) gp[ii * CF] = acc[ii];
}

// ---------------------------------------------------------------------------
// Kernel 3: brute-force top-8 KNN. One thread per query; targets staged in
// smem as float4 (x,y,z,t2). Score s = t2 - 2*q.t (same expansion as ref,
// minus the per-query constant -> identical ordering).
// ---------------------------------------------------------------------------
__device__ __forceinline__ void ins8(float (&dk)[8], int (&ik)[8], float d, int j) {
    dk[7] = d; ik[7] = j;
#pragma unroll
    for (int s = 7; s >= 1; --s) {
        if (dk[s] < dk[s - 1]) {
            float tf = dk[s - 1]; dk[s - 1] = dk[s]; dk[s] = tf;
            int   ti = ik[s - 1]; ik[s - 1] = ik[s]; ik[s] = ti;
        }
    }
}

__global__ void __launch_bounds__(256) knn_kernel(const float* __restrict__ xyz2) {
    __shared__ __align__(16) float4 sP[2048];

    int b = blockIdx.x >> 6;
    int q = (blockIdx.x & 63) * 256 + threadIdx.x;

    const float* xq = xyz2 + (size_t)b * 3 * N2;
    float qx = xq[q], qy = xq[N2 + q], qz = xq[2 * N2 + q];
    float mx = -2.f * qx, my = -2.f * qy, mz = -2.f * qz;

    float dk[8]; int ik[8];
#pragma unroll
    for (int s = 0; s < 8; s++) { dk[s] = 3.4e38f; ik[s] = 0; }

    const float4* P = g_pts + b * N1;

    for (int tile = 0; tile < N1; tile += 2048) {
        __syncthreads();
        for (int i = threadIdx.x; i < 2048; i += 256) sP[i] = P[tile + i];
        __syncthreads();

        for (int j = 0; j < 2048; j += 4) {
            float4 p0 = sP[j + 0], p1 = sP[j + 1], p2 = sP[j + 2], p3 = sP[j + 3];
            float d0 = fmaf(mz, p0.z, fmaf(my, p0.y, fmaf(mx, p0.x, p0.w)));
            float d1 = fmaf(mz, p1.z, fmaf(my, p1.y, fmaf(mx, p1.x, p1.w)));
            float d2 = fmaf(mz, p2.z, fmaf(my, p2.y, fmaf(mx, p2.x, p2.w)));
            float d3 = fmaf(mz, p3.z, fmaf(my, p3.y, fmaf(mx, p3.x, p3.w)));
            float dmin = fminf(fminf(d0, d1), fminf(d2, d3));
            if (dmin < dk[7]) {
                int jb = tile + j;
                if (d0 < dk[7]) ins8(dk, ik, d0, jb + 0);
                if (d1 < dk[7]) ins8(dk, ik, d1, jb + 1);
                if (d2 < dk[7]) ins8(dk, ik, d2, jb + 2);
                if (d3 < dk[7]) ins8(dk, ik, d3, jb + 3);
            }
        }
    }

    int4* op4 = (int4*)(g_idx + ((size_t)b * N2 + q) * KNN);
    op4[0] = make_int4(ik[0], ik[1], ik[2], ik[3]);
    op4[1] = make_int4(ik[4], ik[5], ik[6], ik[7]);
}

// ---------------------------------------------------------------------------
// Kernel 4: finalize. Per query: h_n = lrelu(g[idx_n] - W1_xyz @ q),
// w_j[n] = W2[j] . h_n  (b2 cancels in softmax), softmax over n, dot with flow.
// ---------------------------------------------------------------------------
__device__ __forceinline__ float softmax_dot(const float (&w)[8],
                                             const float* __restrict__ f,
                                             const int (&ik)[8]) {
    float m = w[0];
#pragma unroll
    for (int n = 1; n < 8; n++) m = fmaxf(m, w[n]);
    float s = 0.f, acc = 0.f;
#pragma unroll
    for (int n = 0; n < 8; n++) {
        float e = __expf(w[n] - m);
        s += e;
        acc = fmaf(e, __ldg(f + ik[n]), acc);
    }
    return acc / s;
}

__global__ void __launch_bounds__(256) up_kernel(const float* __restrict__ xyz2,
                                                 const float* __restrict__ flow,
                                                 const float* __restrict__ W1,
                                                 const float* __restrict__ W2,
                                                 float* __restrict__ out) {
    __shared__ float sW2[3 * 64];   // [j][o]
    __shared__ float sWx[64 * 3];   // [o][c]  (xyz columns of W1)
    int t = threadIdx.x;
    if (t < 192) sW2[t] = W2[t];
    if (t < 192) { int o = t / 3, c = t - o * 3; sWx[t] = W1[o * 67 + 64 + c]; }
    __syncthreads();

    int b = blockIdx.x >> 6;
    int q = (blockIdx.x & 63) * 256 + t;

    const float* xq = xyz2 + (size_t)b * 3 * N2;
    float qx = xq[q], qy = xq[N2 + q], qz = xq[2 * N2 + q];

    const int* ip = g_idx + ((size_t)b * N2 + q) * KNN;
    int ik[8];
    {
        int4 a = ((const int4*)ip)[0];
        int4 c4 = ((const int4*)ip)[1];
        ik[0] = a.x; ik[1] = a.y; ik[2] = a.z; ik[3] = a.w;
        ik[4] = c4.x; ik[5] = c4.y; ik[6] = c4.z; ik[7] = c4.w;
    }

    const float* gb = g_gtab + (size_t)b * N1 * CF;

    float a0[8], a1[8], a2[8];
#pragma unroll
    for (int n = 0; n < 8; n++) { a0[n] = 0.f; a1[n] = 0.f; a2[n] = 0.f; }

#pragma unroll 4
    for (int o4 = 0; o4 < 16; o4++) {
        int ob = o4 * 4;
        float uu[4], wa[4], wb[4], wc[4];
#pragma unroll
        for (int i = 0; i < 4; i++) {
            int o = ob + i;
            uu[i] = fmaf(sWx[o * 3 + 2], qz, fmaf(sWx[o * 3 + 1], qy, sWx[o * 3] * qx));
            wa[i] = sW2[o];
            wb[i] = sW2[64 + o];
            wc[i] = sW2[128 + o];
        }
#pragma unroll
        for (int n = 0; n < 8; n++) {
            float4 g4 = ((const float4*)(gb + (size_t)ik[n] * CF))[o4];
            float h;
            h = g4.x - uu[0]; h = h >= 0.f ? h : 0.1f * h;
            a0[n] = fmaf(wa[0], h, a0[n]); a1[n] = fmaf(wb[0], h, a1[n]); a2[n] = fmaf(wc[0], h, a2[n]);
            h = g4.y - uu[1]; h = h >= 0.f ? h : 0.1f * h;
            a0[n] = fmaf(wa[1], h, a0[n]); a1[n] = fmaf(wb[1], h, a1[n]); a2[n] = fmaf(wc[1], h, a2[n]);
            h = g4.z - uu[2]; h = h >= 0.f ? h : 0.1f * h;
            a0[n] = fmaf(wa[2], h, a0[n]); a1[n] = fmaf(wb[2], h, a1[n]); a2[n] = fmaf(wc[2], h, a2[n]);
            h = g4.w - uu[3]; h = h >= 0.f ? h : 0.1f * h;
            a0[n] = fmaf(wa[3], h, a0[n]); a1[n] = fmaf(wb[3], h, a1[n]); a2[n] = fmaf(wc[3], h, a2[n]);
        }
    }

    const float* fb = flow + (size_t)b * 3 * N1;
    float* ob_ = out + (size_t)b * 3 * N2;
    ob_[q]          = softmax_dot(a0, fb, ik);
    ob_[N2 + q]     = softmax_dot(a1, fb + N1, ik);
    ob_[2 * N2 + q] = softmax_dot(a2, fb + 2 * N1, ik);
}

// ---------------------------------------------------------------------------
extern "C" void kernel_launch(void* const* d_in, const int* in_sizes, int n_in,
                              void* d_out, int out_size) {
    const float* xyz1  = (const float*)d_in[0];
    const float* xyz2  = (const float*)d_in[1];
    const float* feat1 = (const float*)d_in[2];
    const float* flow  = (const float*)d_in[3];
    const float* W1    = (const float*)d_in[4];
    const float* b1    = (const float*)d_in[5];
    const float* W2    = (const float*)d_in[6];
    // b2 (d_in[7]) intentionally unused: constant shift cancels in softmax over k.
    float* out = (float*)d_out;

    pack_kernel<<<(NB * N1 + 255) / 256, 256>>>(xyz1);
    gmat_kernel<<<NB * 64, 256>>>(feat1, xyz1, W1, b1);
    knn_kernel<<<NB * 64, 256>>>(xyz2);
    up_kernel<<<NB * 64, 256>>>(xyz2, flow, W1, W2, out);
}